// round 16
// baseline (speedup 1.0000x reference)
#include <cuda_runtime.h>

#define BB   4
#define SEQ  4096
#define CH   512
#define NH   8
#define HD   64
#define MM   1024
#define LN_EPS 1e-5f
#define LOG2E 1.44269504088896340736f

// ---------------- scratch ----------------
__device__ float g_q   [BB*NH*SEQ*HD];   // raw fp32, [b*h][n][d]
__device__ float g_k_kp[BB*NH*SEQ*HD];   // K tensor, K-perm, tf32-rounded
__device__ float g_k_vp[BB*NH*SEQ*HD];   // K tensor, V-perm, tf32-rounded
__device__ float g_v_kp[BB*NH*SEQ*HD];   // V tensor, K-perm, tf32-rounded
__device__ float g_v_vp[BB*NH*SEQ*HD];   // V tensor, V-perm, tf32-rounded
__device__ float g_xr  [BB*MM*HD];       // raw fp32
__device__ float g_kc  [BB*NH*MM*HD];    // compressed K, K-perm, tf32-rounded
__device__ float g_vc  [BB*NH*MM*HD];    // compressed V, V-perm, tf32-rounded
__device__ float g_o   [BB*SEQ*CH];      // tf32-rounded + kperm-along-CH (proj A)
__device__ float g_xrd [BB*SEQ*CH];      // x, tf32-rounded + kperm-along-k
__device__ float g_wq  [CH*3*CH];        // w_qkv, tf32-rounded, vperm-along-k
__device__ float g_wp  [CH*CH];          // w_proj, tf32-rounded, vperm-along-k

// ---------------- tf32 mma helpers ----------------
__device__ __forceinline__ unsigned f2tf(float f) {
    unsigned u;
    asm("cvt.rna.tf32.f32 %0, %1;" : "=r"(u) : "f"(f));
    return u;
}
__device__ __forceinline__ float ex2(float x) {
    float r;
    asm("ex2.approx.ftz.f32 %0, %1;" : "=f"(r) : "f"(x));
    return r;
}
__device__ __forceinline__ void mma8(float c[4], unsigned a0, unsigned a1,
                                     unsigned a2, unsigned a3,
                                     unsigned b0, unsigned b1) {
    asm volatile(
        "mma.sync.aligned.m16n8k8.row.col.f32.tf32.tf32.f32 "
        "{%0,%1,%2,%3},{%4,%5,%6,%7},{%8,%9},{%0,%1,%2,%3};"
        : "+f"(c[0]), "+f"(c[1]), "+f"(c[2]), "+f"(c[3])
        : "r"(a0), "r"(a1), "r"(a2), "r"(a3), "r"(b0), "r"(b1));
}
__device__ __forceinline__ unsigned smem_u32(const void* p) {
    return (unsigned)__cvta_generic_to_shared(p);
}
#define CP16(dst_u32, src_ptr) \
    asm volatile("cp.async.cg.shared.global [%0], [%1], 16;" :: "r"(dst_u32), "l"(src_ptr))
#define CP_COMMIT()  asm volatile("cp.async.commit_group;")
#define CP_WAIT0()   asm volatile("cp.async.wait_group 0;")

// K-perm: within an 8-dim block, pairs (t, t+4) adjacent: u -> 2*(u&3) + (u>>2)
__device__ __forceinline__ int kperm_col(int d) {
    int u = d & 7;
    return (d & ~7) | ((u & 3) << 1) | (u >> 2);
}

// ======================================================================
// pre-round kernels (unchanged): tf32 bits + mma-friendly permutations
// ======================================================================
__global__ void round_kperm_kernel(const float* __restrict__ in,
                                   float* __restrict__ out, int n8)
{
    int i = blockIdx.x * 256 + threadIdx.x;
    int stride = gridDim.x * 256;
    for (; i < n8; i += stride) {
        const float4* p = (const float4*)(in + (long)i * 8);
        float4 v0 = p[0], v1 = p[1];
        uint4 a = make_uint4(f2tf(v0.x), f2tf(v1.x), f2tf(v0.y), f2tf(v1.y));
        uint4 b = make_uint4(f2tf(v0.z), f2tf(v1.z), f2tf(v0.w), f2tf(v1.w));
        uint4* q = (uint4*)(out + (long)i * 8);
        q[0] = a; q[1] = b;
    }
}

__global__ void round_vpermk_kernel(const float* __restrict__ in,
                                    float* __restrict__ out, int N, int total)
{
    int i = blockIdx.x * 256 + threadIdx.x;
    int stride = gridDim.x * 256;
    const int nq = N >> 2;
    for (; i < total; i += stride) {
        int pr = i / nq, n = (i % nq) << 2;
        int k0 = (pr >> 2) * 8 + (pr & 3);
        float4 a = *(const float4*)(in + (long)k0 * N + n);
        float4 b = *(const float4*)(in + (long)(k0 + 4) * N + n);
        uint4 o0 = make_uint4(f2tf(a.x), f2tf(b.x), f2tf(a.y), f2tf(b.y));
        uint4 o1 = make_uint4(f2tf(a.z), f2tf(b.z), f2tf(a.w), f2tf(b.w));
        uint4* q = (uint4*)(out + (long)pr * 2 * N + 2 * n);
        q[0] = o0; q[1] = o1;
    }
}

// ======================================================================
// GEMM core: 128 threads = 4 warps (2x2), warp tile 64x64.
// 128 mmas per warp per ktile (2x barrier amortization vs R15).
// A kperm'd (LDS.64 pairs), B vperm'd (LDS.64), k-tile 32 double-buffered.
// ======================================================================
#define APAD 40
#define BPR  264
#define GET  128
#define GE_SMEM ((2*128*APAD + 2*16*BPR) * (int)sizeof(float))

__device__ __forceinline__ void ge_prefetch(
    const float* __restrict__ A, int lda,
    const float* __restrict__ Bp, int ldb2,
    int bm, int bn, float* As, float* Bs, int kt, int tid)
{
    float* Ab = As + (kt & 1) * 128 * APAD;
    float* Bb = Bs + (kt & 1) * 16 * BPR;
    const int k0 = kt * 32;
    #pragma unroll
    for (int it = 0; it < 8; it++) {
        int s = tid + it * GET;
        int r = s >> 3, seg = (s & 7) << 2;
        CP16(smem_u32(Ab + r*APAD + seg), A + (long)(bm + r)*lda + k0 + seg);
    }
    #pragma unroll
    for (int it = 0; it < 8; it++) {
        int s = tid + it * GET;
        int rb = s >> 6, segb = (s & 63) << 2;
        CP16(smem_u32(Bb + rb*BPR + segb),
             Bp + (long)(16*kt + rb)*ldb2 + 2*bn + segb);
    }
    CP_COMMIT();
}

__device__ __forceinline__ void gemm_core_tf32(
    const float* __restrict__ A, int lda,
    const float* __restrict__ Bp, int ldb2,
    int bm, int bn, float* sm, int tid, float cfr[4][8][4])
{
    float* As = sm;
    float* Bs = sm + 2*128*APAD;
    const int w = tid >> 5, lane = tid & 31;
    const int g = lane >> 2, t = lane & 3;
    const int wm = (w >> 1) * 64, wn = (w & 1) * 64;

    ge_prefetch(A, lda, Bp, ldb2, bm, bn, As, Bs, 0, tid);
    const int NKT = lda / 32;
    for (int kt = 0; kt < NKT; kt++) {
        CP_WAIT0();
        __syncthreads();
        if (kt + 1 < NKT)
            ge_prefetch(A, lda, Bp, ldb2, bm, bn, As, Bs, kt + 1, tid);

        const unsigned* Au = (const unsigned*)(As + (kt & 1)*128*APAD);
        const unsigned* Bu = (const unsigned*)(Bs + (kt & 1)*16*BPR);
        #pragma unroll
        for (int ks = 0; ks < 4; ks++) {
            unsigned af[4][4];
            #pragma unroll
            for (int mt = 0; mt < 4; mt++) {
                const unsigned* ap = Au + (wm + mt*16 + g)*APAD + ks*8 + 2*t;
                uint2 lo = *(const uint2*)ap;
                uint2 hi = *(const uint2*)(ap + 8*APAD);
                af[mt][0] = lo.x; af[mt][1] = hi.x;
                af[mt][2] = lo.y; af[mt][3] = hi.y;
            }
            uint2 bf[8];
            #pragma unroll
            for (int nt = 0; nt < 8; nt++)
                bf[nt] = *(const uint2*)(Bu + (ks*4 + t)*BPR + 2*(wn + nt*8 + g));
            #pragma unroll
            for (int mt = 0; mt < 4; mt++)
                #pragma unroll
                for (int nt = 0; nt < 8; nt++)
                    mma8(cfr[mt][nt], af[mt][0], af[mt][1], af[mt][2], af[mt][3],
                         bf[nt].x, bf[nt].y);
        }
    }
}

__global__ __launch_bounds__(GET, 2)
void qkv_mma_kernel()
{
    extern __shared__ float sm[];
    float cfr[4][8][4];
    #pragma unroll
    for (int a = 0; a < 4; a++)
        #pragma unroll
        for (int b = 0; b < 8; b++)
            #pragma unroll
            for (int c = 0; c < 4; c++) cfr[a][b][c] = 0.f;

    const int tid = threadIdx.x;
    const int bm = blockIdx.y * 128, bn = blockIdx.x * 128;
    gemm_core_tf32(g_xrd, 512, g_wq, 2*3*CH, bm, bn, sm, tid, cfr);

    const int w = tid >> 5, lane = tid & 31;
    const int g = lane >> 2, t = lane & 3;
    const int wm = (w >> 1) * 64, wn = (w & 1) * 64;
    #pragma unroll
    for (int mt = 0; mt < 4; mt++)
        #pragma unroll
        for (int nt = 0; nt < 8; nt++)
            #pragma unroll
            for (int rr = 0; rr < 2; rr++)
                #pragma unroll
                for (int cc = 0; cc < 2; cc++) {
                    int row = bm + wm + mt*16 + g + rr*8;
                    int col = bn + wn + nt*8 + 2*t + cc;
                    int b_ = row >> 12, n = row & 4095;
                    int tc = col >> 9, rem = col & 511;
                    int hh = rem >> 6, d = rem & 63;
                    float val = cfr[mt][nt][rr*2 + cc];
                    long base = ((long)(b_*NH + hh)) * SEQ;
                    if (tc == 0) {
                        g_q[(base + n)*HD + d] = val;
                    } else {
                        float rv = __uint_as_float(f2tf(val));
                        float* kp = (tc == 1) ? g_k_kp : g_v_kp;
                        float* vp = (tc == 1) ? g_k_vp : g_v_vp;
                        kp[(base + n)*HD + kperm_col(d)] = rv;
                        long pr = (long)(n >> 3) * 4 + (n & 3);
                        vp[base*HD + pr*128 + 2*d + ((n >> 2) & 1)] = rv;
                    }
                }
}

__global__ __launch_bounds__(GET, 2)
void proj_mma_kernel(const float* __restrict__ bias, float* __restrict__ Out)
{
    extern __shared__ float sm[];
    float cfr[4][8][4];
    #pragma unroll
    for (int a = 0; a < 4; a++)
        #pragma unroll
        for (int b = 0; b < 8; b++)
            #pragma unroll
            for (int c = 0; c < 4; c++) cfr[a][b][c] = 0.f;

    const int tid = threadIdx.x;
    const int bm = blockIdx.y * 128, bn = blockIdx.x * 128;
    gemm_core_tf32(g_o, 512, g_wp, 2*CH, bm, bn, sm, tid, cfr);

    const int w = tid >> 5, lane = tid & 31;
    const int g = lane >> 2, t = lane & 3;
    const int wm = (w >> 1) * 64, wn = (w & 1) * 64;
    #pragma unroll
    for (int mt = 0; mt < 4; mt++)
        #pragma unroll
        for (int nt = 0; nt < 8; nt++)
            #pragma unroll
            for (int rr = 0; rr < 2; rr++) {
                long row = bm + wm + mt*16 + g + rr*8;
                int col = bn + wn + nt*8 + 2*t;
                float2 o = make_float2(cfr[mt][nt][rr*2]     + bias[col],
                                       cfr[mt][nt][rr*2 + 1] + bias[col + 1]);
                *(float2*)(Out + row*CH + col) = o;
            }
}

// ======================================================================
// SR branch (unchanged)
// ======================================================================
__global__ void sr_kernel(const float* __restrict__ x,
                          const float* __restrict__ wconv, const float* __restrict__ bconv,
                          const float* __restrict__ lns,   const float* __restrict__ lnb,
                          const float* __restrict__ wlin,  const float* __restrict__ blin)
{
    __shared__ float y[CH];
    __shared__ float red[2][4];
    const int bm = blockIdx.x;
    const int b_ = bm >> 10, m = bm & 1023;
    const int i = m >> 5, j = m & 31;
    const int tid = threadIdx.x;
    const float* xb = x + (long)b_ * SEQ * CH;
    const int n00 = (2*i) * 64 + 2*j;

    float lsum = 0.f, lsq = 0.f;
    for (int c = tid; c < CH; c += 128) {
        float4 w = *(const float4*)(wconv + c * 4);
        float v = bconv[c];
        v = fmaf(xb[(long)(n00     ) * CH + c], w.x, v);
        v = fmaf(xb[(long)(n00 +  1) * CH + c], w.y, v);
        v = fmaf(xb[(long)(n00 + 64) * CH + c], w.z, v);
        v = fmaf(xb[(long)(n00 + 65) * CH + c], w.w, v);
        y[c] = v;
        lsum += v; lsq += v * v;
    }
    #pragma unroll
    for (int off = 16; off; off >>= 1) {
        lsum += __shfl_xor_sync(0xffffffffu, lsum, off);
        lsq  += __shfl_xor_sync(0xffffffffu, lsq,  off);
    }
    if ((tid & 31) == 0) { red[0][tid >> 5] = lsum; red[1][tid >> 5] = lsq; }
    __syncthreads();
    float tsum = red[0][0] + red[0][1] + red[0][2] + red[0][3];
    float tsq  = red[1][0] + red[1][1] + red[1][2] + red[1][3];
    float mu   = tsum * (1.f / CH);
    float var  = tsq * (1.f / CH) - mu * mu;
    float rstd = rsqrtf(var + LN_EPS);
    for (int c = tid; c < CH; c += 128)
        y[c] = (y[c] - mu) * rstd * lns[c] + lnb[c];
    __syncthreads();
    if (tid < HD) {
        const int d = tid;
        float a = blin[d];
        for (int c = 0; c < CH; c++)
            a = fmaf(y[c], wlin[c * HD + d], a);
        g_xr[(long)bm * HD + d] = a;
    }
}

// ======================================================================
// Flash attention body (unchanged): 128 thr = 4 warps, 32 rows per warp,
// 2 CTAs/SM, double-buffered K/V, un-maxed softmax.
// omode: 0 = kperm rounded stride CH (feeds proj), 1 = K-perm rounded HD,
//        2 = V-perm rounded
// ======================================================================
#define TQ 128
#define TK 64
#define FLT 128
#define QPAD 68
#define KPAD 72
#define VSP  136
#define KBUF (TK*KPAD)
#define VBUF (32*VSP)
#define FL_SMEM ((TQ*QPAD + 2*KBUF + 2*VBUF) * (int)sizeof(float))

__device__ __forceinline__ void flash_prefetch(
    float* Ks, float* Vs, const float* __restrict__ Kg,
    const float* __restrict__ Vg, int chunk, int tid)
{
    float* kb = Ks + (chunk & 1) * KBUF;
    float* vb = Vs + (chunk & 1) * VBUF;
    const float* Kc = Kg + (long)chunk * TK * HD;
    const float* Vc = Vg + (long)chunk * 32 * 128;
    #pragma unroll
    for (int it = 0; it < 8; it++) {
        int s = tid + it * FLT;
        int kr = s >> 4, ks4 = (s & 15) << 2;
        CP16(smem_u32(kb + kr*KPAD + ks4), Kc + (long)kr*HD + ks4);
        int vr = s >> 5, vseg = (s & 31) << 2;
        CP16(smem_u32(vb + vr*VSP + vseg), Vc + (long)vr*128 + vseg);
    }
    CP_COMMIT();
}

__device__ __forceinline__ void flash_body(
    const float* __restrict__ Q, const float* __restrict__ Kg,
    const float* __restrict__ Vg, float* __restrict__ O,
    int nk, float qscale, int ostride, int omode)
{
    extern __shared__ float sm[];
    float* Ps = sm;                    // [TQ][QPAD]  (P, tf32 bits)
    float* Ks = sm + TQ*QPAD;          // [2][TK][KPAD]
    float* Vs = Ks + 2*KBUF;           // [2][32][VSP]

    const int tid = threadIdx.x;
    const int w = tid >> 5, lane = tid & 31;
    const int g = lane >> 2, t = lane & 3;
    const int qrow0 = blockIdx.x * TQ;
    const int r_base = w * 32;
    const int nchunks = nk / TK;

    flash_prefetch(Ks, Vs, Kg, Vg, 0, tid);

    unsigned qf[2][8][4];
    #pragma unroll
    for (int mt = 0; mt < 2; mt++) {
        const float* q0 = Q + (long)(qrow0 + r_base + 16*mt + g) * HD;
        const float* q1 = q0 + 8 * HD;
        #pragma unroll
        for (int kk = 0; kk < 8; kk++) {
            qf[mt][kk][0] = f2tf(q0[kk*8 + t]     * qscale);
            qf[mt][kk][1] = f2tf(q1[kk*8 + t]     * qscale);
            qf[mt][kk][2] = f2tf(q0[kk*8 + t + 4] * qscale);
            qf[mt][kk][3] = f2tf(q1[kk*8 + t + 4] * qscale);
        }
    }

    float oacc[2][8][4];
    #pragma unroll
    for (int mt = 0; mt < 2; mt++)
        #pragma unroll
        for (int nt = 0; nt < 8; nt++)
            #pragma unroll
            for (int c = 0; c < 4; c++) oacc[mt][nt][c] = 0.f;
    float lrow[2][2] = {{0.f, 0.f}, {0.f, 0.f}};

    unsigned* Pu = (unsigned*)Ps;

    for (int c = 0; c < nchunks; c++) {
        CP_WAIT0();
        __syncthreads();
        if (c + 1 < nchunks)
            flash_prefetch(Ks, Vs, Kg, Vg, c + 1, tid);

        const unsigned* Ku = (const unsigned*)(Ks + (c & 1) * KBUF);
        const unsigned* Vu = (const unsigned*)(Vs + (c & 1) * VBUF);

        #pragma unroll
        for (int qg = 0; qg < 4; qg++) {
            float sfr[2][2][4];
            #pragma unroll
            for (int mt = 0; mt < 2; mt++)
                #pragma unroll
                for (int jt = 0; jt < 2; jt++)
                    #pragma unroll
                    for (int cc = 0; cc < 4; cc++) sfr[mt][jt][cc] = 0.f;
            #pragma unroll
            for (int kk = 0; kk < 8; kk++) {
                #pragma unroll
                for (int jt = 0; jt < 2; jt++) {
                    uint2 b = *(const uint2*)(Ku + ((qg*2 + jt)*8 + g)*KPAD + kk*8 + 2*t);
                    mma8(sfr[0][jt], qf[0][kk][0], qf[0][kk][1], qf[0][kk][2], qf[0][kk][3], b.x, b.y);
                    mma8(sfr[1][jt], qf[1][kk][0], qf[1][kk][1], qf[1][kk][2], qf[1][kk][3], b.x, b.y);
                }
            }
            #pragma unroll
            for (int mt = 0; mt < 2; mt++) {
                int rl = r_base + 16*mt + g;
                #pragma unroll
                for (int jt = 0; jt < 2; jt++) {
                    float e0 = ex2(sfr[mt][jt][0]);
                    float e1 = ex2(sfr[mt][jt][1]);
                    float e2 = ex2(sfr[mt][jt][2]);
                    float e3 = ex2(sfr[mt][jt][3]);
                    lrow[mt][0] += e0 + e1;
                    lrow[mt][1] += e2 + e3;
                    *(uint2*)(Pu + rl*QPAD + (qg*2 + jt)*8 + 2*t) =
                        make_uint2(f2tf(e0), f2tf(e1));
                    *(uint2*)(Pu + (rl + 8)*QPAD + (qg*2 + jt)*8 + 2*t) =
                        make_uint2(f2tf(e2), f2tf(e3));
                }
            }
        }
        __syncwarp();

        #pragma unroll
        for (int kk = 0; kk < 8; kk++) {
            unsigned a[2][4];
            #pragma unroll
            for (int mt = 0; mt < 2; mt++) {
                const unsigned* pp = Pu + (r_base + 16*mt + g)*QPAD + kk*8 + t;
                a[mt][0] = pp[0];
                a[mt][1] = pp[8*QPAD];
                a[mt][2] = pp[4];
                a[mt][3] = pp[8*QPAD + 4];
            }
            const unsigned* vrow = Vu + (kk*4 + t)*VSP;
            #pragma unroll
            for (int nt = 0; nt < 8; nt++) {
                uint2 b = *(const uint2*)(vrow + (nt*8 + g)*2);
                mma8(oacc[0][nt], a[0][0], a[0][1], a[0][2], a[0][3], b.x, b.y);
                mma8(oacc[1][nt], a[1][0], a[1][1], a[1][2], a[1][3], b.x, b.y);
            }
        }
    }

    // epilogue
    #pragma unroll
    for (int mt = 0; mt < 2; mt++) {
        lrow[mt][0] += __shfl_xor_sync(0xffffffffu, lrow[mt][0], 1);
        lrow[mt][0] += __shfl_xor_sync(0xffffffffu, lrow[mt][0], 2);
        lrow[mt][1] += __shfl_xor_sync(0xffffffffu, lrow[mt][1], 1);
        lrow[mt][1] += __shfl_xor_sync(0xffffffffu, lrow[mt][1], 2);
        #pragma unroll
        for (int rr = 0; rr < 2; rr++) {
            float inv = 1.f / lrow[mt][rr];
            int j = qrow0 + r_base + 16*mt + g + rr*8;
            #pragma unroll
            for (int nt = 0; nt < 8; nt++) {
                float v0 = oacc[mt][nt][rr*2]     * inv;
                float v1 = oacc[mt][nt][rr*2 + 1] * inv;
                int c0 = nt*8 + 2*t;
                if (omode <= 1) {
                    O[(long)j*ostride + kperm_col(c0)]     = __uint_as_float(f2tf(v0));
                    O[(long)j*ostride + kperm_col(c0 + 1)] = __uint_as_float(f2tf(v1));
                } else {
                    long pb = ((long)(j >> 3)*4 + (j & 3))*128 + ((j >> 2) & 1);
                    O[pb + 2*c0]       = __uint_as_float(f2tf(v0));
                    O[pb + 2*(c0 + 1)] = __uint_as_float(f2tf(v1));
                }
            }
        }
    }
}

// fused K+V compression: z in [0,64): z<32 -> K branch, else V branch
__global__ __launch_bounds__(FLT, 2)
void compress_kernel()
{
    const int z = blockIdx.z;
    const int zz = z & 31;                  // b*NH + h
    const float* Kp = ((z < 32) ? g_k_kp : g_v_kp) + (long)zz * SEQ * HD;
    const float* Vp = ((z < 32) ? g_k_vp : g_v_vp) + (long)zz * SEQ * HD;
    float* O        = ((z < 32) ? g_kc   : g_vc  ) + (long)zz * MM * HD;
    const float* Q = g_xr + (long)(zz / NH) * MM * HD;
    flash_body(Q, Kp, Vp, O, SEQ, LOG2E, HD, (z < 32) ? 1 : 2);
}

// main attention: z in [0,32)
__global__ __launch_bounds__(FLT, 2)
void attn_kernel()
{
    const int z = blockIdx.z;
    const float* Q = g_q  + (long)z * SEQ * HD;
    const float* K = g_kc + (long)z * MM * HD;
    const float* V = g_vc + (long)z * MM * HD;
    float* O = g_o + (long)(z / NH) * SEQ * CH + (long)(z % NH) * HD;
    flash_body(Q, K, V, O, MM, 0.125f * LOG2E, CH, 0);
}

// ======================================================================
extern "C" void kernel_launch(void* const* d_in, const int* in_sizes, int n_in,
                              void* d_out, int out_size)
{
    const float* x        = (const float*)d_in[0];
    const float* w_qkv    = (const float*)d_in[1];
    const float* w_proj   = (const float*)d_in[2];
    const float* b_proj   = (const float*)d_in[3];
    const float* w_sr_c   = (const float*)d_in[4];
    const float* b_sr_c   = (const float*)d_in[5];
    const float* lns      = (const float*)d_in[6];
    const float* lnb      = (const float*)d_in[7];
    const float* w_sr_lin = (const float*)d_in[8];
    const float* b_sr_lin = (const float*)d_in[9];
    float* out = (float*)d_out;

    void *pxrd, *pwq, *pwp;
    cudaGetSymbolAddress(&pxrd, g_xrd);
    cudaGetSymbolAddress(&pwq,  g_wq);
    cudaGetSymbolAddress(&pwp,  g_wp);

    cudaFuncSetAttribute(compress_kernel, cudaFuncAttributeMaxDynamicSharedMemorySize, FL_SMEM);
    cudaFuncSetAttribute(attn_kernel,     cudaFuncAttributeMaxDynamicSharedMemorySize, FL_SMEM);
    cudaFuncSetAttribute(qkv_mma_kernel,  cudaFuncAttributeMaxDynamicSharedMemorySize, GE_SMEM);
    cudaFuncSetAttribute(proj_mma_kernel, cudaFuncAttributeMaxDynamicSharedMemorySize, GE_SMEM);

    // 0) pre-round + permute GEMM operands
    round_kperm_kernel <<<4096, 256>>>(x,      (float*)pxrd, BB*SEQ*CH/8);
    round_vpermk_kernel<<<384,  256>>>(w_qkv,  (float*)pwq,  3*CH, (CH/2)*(3*CH/4));
    round_vpermk_kernel<<<128,  256>>>(w_proj, (float*)pwp,  CH,   (CH/2)*(CH/4));

    // 1) QKV projection (4-warp wide-tile GEMM)
    qkv_mma_kernel<<<dim3(12, 128), GET, GE_SMEM>>>();

    // 2) SR branch -> g_xr
    sr_kernel<<<BB * MM, 128>>>(x, w_sr_c, b_sr_c, lns, lnb, w_sr_lin, b_sr_lin);

    // 3+4) fused K/V compression
    compress_kernel<<<dim3(MM / TQ, 1, 2 * BB * NH), FLT, FL_SMEM>>>();

    // 5) main attention -> g_o (rounded + kperm'd for proj)
    attn_kernel<<<dim3(SEQ / TQ, 1, BB * NH), FLT, FL_SMEM>>>();

    // 6) output projection (4-warp wide-tile GEMM)
    proj_mma_kernel<<<dim3(4, 128), GET, GE_SMEM>>>(b_proj, out);
}